// round 15
// baseline (speedup 1.0000x reference)
#include <cuda_runtime.h>
#include <cuda_fp16.h>
#include <cstdint>

#define NROW 8192
#define TOTUNITS 2080                 // 64*65/2 upper-triangle tiles
#define NCLS 100
#define TEN_LOG2E 14.4269504088896f   // 10 * log2(e)

// -------------------- device globals (no allocations allowed) ---------------
// Invariant: g_S and g_cnt are ZERO on entry to kernel_launch. True at module
// load (CUDA zero-init) and restored by finalize_kernel at the end of every
// call — so every call performs identical work on identical state.
__device__ __align__(256) __half g_eH[NROW * 128];  // normalized, fp16
__device__ __align__(256) int g_lab[NROW];
__device__ float g_sumexp[NROW];
__device__ float g_dii[NROW];          // fp32 self-dot of the fp16 row
__device__ __align__(256) float g_S[NCLS * 128];    // per-class sums
__device__ int g_cnt[NCLS];

// -------------------- PTX helpers (base ISA only) ---------------------------
__device__ __forceinline__ uint32_t smem_u32(const void* p) {
    uint32_t a;
    asm("{ .reg .u64 t; cvta.to.shared.u64 t, %1; cvt.u32.u64 %0, t; }" : "=r"(a) : "l"(p));
    return a;
}
__device__ __forceinline__ float ex2f(float x) {
    float y; asm("ex2.approx.f32 %0, %1;" : "=f"(y) : "f"(x)); return y;
}
__device__ __forceinline__ void cp16(uint32_t dst, const void* src) {
    asm volatile("cp.async.cg.shared.global [%0], [%1], 16;" :: "r"(dst), "l"(src));
}
#define CP_COMMIT() asm volatile("cp.async.commit_group;" ::: "memory")
#define CP_WAIT1()  asm volatile("cp.async.wait_group 1;" ::: "memory")

__device__ __forceinline__ void ldsm4(uint32_t* r, uint32_t addr) {
    asm volatile("ldmatrix.sync.aligned.m8n8.x4.shared.b16 {%0,%1,%2,%3}, [%4];"
        : "=r"(r[0]), "=r"(r[1]), "=r"(r[2]), "=r"(r[3]) : "r"(addr));
}
__device__ __forceinline__ void mma16816(float* d, const uint32_t* a, const uint32_t* b) {
    asm volatile(
        "mma.sync.aligned.m16n8k16.row.col.f32.f16.f16.f32 "
        "{%0,%1,%2,%3}, {%4,%5,%6,%7}, {%8,%9}, {%0,%1,%2,%3};"
        : "+f"(d[0]), "+f"(d[1]), "+f"(d[2]), "+f"(d[3])
        : "r"(a[0]), "r"(a[1]), "r"(a[2]), "r"(a[3]), "r"(b[0]), "r"(b[1]));
}

// Tile: 128 rows x 256B (128 fp16); 16B chunk c stored at c ^ (r & 7).
// Cooperative load by all 256 threads (8 cp.async each).
__device__ __forceinline__ void load_tile(uint32_t dst, const __half* g, int tid) {
    const char* gb = (const char*)g;
    #pragma unroll
    for (int it = 0; it < 8; ++it) {
        int q = tid + it * 256;
        int r = q >> 4, c = q & 15;
        cp16(dst + r * 256 + ((c ^ (r & 7)) * 16), gb + r * 256 + c * 16);
    }
}

__device__ __forceinline__ int tri_off(int bi) { return bi * (129 - bi) / 2; }

// ---------------------------------------------------------------------------
// Kernel 1: label sniff (warp ballot) + convert, L2-normalize, fp16 convert,
// self-dot, class-sum atomics (g_S/g_cnt zero on entry per invariant);
// zeroes g_sumexp for the sim phase. One warp per row.
// ---------------------------------------------------------------------------
__global__ void prep_kernel(const float* __restrict__ emb,
                            const int* __restrict__ raw) {
    const int gtid = blockIdx.x * blockDim.x + threadIdx.x;
    const int row = gtid >> 5;
    const int lane = gtid & 31;

    // dtype sniff: odd 32-bit words 1..63. int64 => all high words zero.
    // int32 => 32 labels, all-zero with prob 1e-64 (and the dataset is fixed).
    const int odd = raw[2 * lane + 1];
    const bool is32 = (__ballot_sync(0xffffffffu, odd != 0) != 0u);
    const int lab = is32 ? raw[row] : raw[2 * row];
    if (lane == 0) { g_lab[row] = lab; g_sumexp[row] = 0.f; }

    float4 v = reinterpret_cast<const float4*>(emb + (size_t)row * 128)[lane];
    float ss = v.x * v.x + v.y * v.y + v.z * v.z + v.w * v.w;
    #pragma unroll
    for (int off = 16; off; off >>= 1) ss += __shfl_xor_sync(0xffffffffu, ss, off);
    float inv = 1.0f / fmaxf(sqrtf(ss), 1e-12f);
    __half2 h0 = __floats2half2_rn(v.x * inv, v.y * inv);
    __half2 h1 = __floats2half2_rn(v.z * inv, v.w * inv);
    uint2 pk;
    pk.x = *reinterpret_cast<uint32_t*>(&h0);
    pk.y = *reinterpret_cast<uint32_t*>(&h1);
    reinterpret_cast<uint2*>(g_eH + (size_t)row * 128)[lane] = pk;

    float2 f0 = __half22float2(h0), f1 = __half22float2(h1);
    float d2 = f0.x * f0.x + f0.y * f0.y + f1.x * f1.x + f1.y * f1.y;
    #pragma unroll
    for (int off = 16; off; off >>= 1) d2 += __shfl_xor_sync(0xffffffffu, d2, off);
    if (lane == 0) g_dii[row] = d2;

    float* sc = g_S + lab * 128 + 4 * lane;
    atomicAdd(sc + 0, f0.x);
    atomicAdd(sc + 1, f0.y);
    atomicAdd(sc + 2, f1.x);
    atomicAdd(sc + 3, f1.y);
    if (lane == 0) atomicAdd(&g_cnt[lab], 1);
}

// ---------------------------------------------------------------------------
// Kernel 2: persistent fp16 HMMA, upper triangle, 8 warps (64x32 warp tile).
// A fragments register-cached per segment; B via ldsm4.  [round-14, verbatim]
// ---------------------------------------------------------------------------
__global__ __launch_bounds__(256, 1) void sim_kernel() {
    extern __shared__ char smem[];
    const uint32_t sbase = smem_u32(smem);
    const uint32_t abase = (sbase + 1023) & ~1023u;
    const uint32_t offA = abase;
    const uint32_t offB[3] = {abase + 32768, abase + 65536, abase + 98304};

    const int tid = threadIdx.x, lane = tid & 31, wid = tid >> 5;
    const int wm = wid & 1, wn = wid >> 1;

    const int asw = lane & 7;
    const uint32_t aRow = offA + (wm * 64 + (lane & 15)) * 256;
    const int aHalf = lane >> 4;
    const uint32_t bRow4 = (wn * 32 + ((lane >> 4) << 3) + (lane & 7)) * 256;
    const int bSel = (lane >> 3) & 1;
    const int bXor = lane & 7;

    const int G = gridDim.x, cta = blockIdx.x;
    int u = (int)(((long long)cta * TOTUNITS) / G);
    const int w1 = (int)(((long long)(cta + 1) * TOTUNITS) / G);

    while (u < w1) {
        int bi = (int)((129.0 - sqrt(129.0 * 129.0 - 8.0 * (double)u)) * 0.5);
        while (tri_off(bi) > u) --bi;
        while (tri_off(bi + 1) <= u) ++bi;
        const int offbi = tri_off(bi);
        const int wend = min(w1, tri_off(bi + 1));
        const int i0 = bi * 128;

        __syncthreads();   // prev segment's buffer reads complete
        load_tile(offA, g_eH + (size_t)i0 * 128, tid);
        load_tile(offB[u % 3], g_eH + (size_t)(bi + (u - offbi)) * 128 * 128, tid);
        CP_COMMIT();       // group: A + B(u)
        if (u + 1 < wend)
            load_tile(offB[(u + 1) % 3],
                      g_eH + (size_t)(bi + (u + 1 - offbi)) * 128 * 128, tid);
        CP_COMMIT();       // group: B(u+1)
        CP_WAIT1();        // A + B(u) landed
        __syncthreads();

        // cache ALL A fragments for this segment (128 regs)
        uint32_t aF[4][8][4];
        #pragma unroll
        for (int mi = 0; mi < 4; ++mi)
            #pragma unroll
            for (int ks = 0; ks < 8; ++ks)
                ldsm4(aF[mi][ks], aRow + mi * 4096 + (((2 * ks + aHalf) ^ asw) << 4));

        float se[8];
        #pragma unroll
        for (int x = 0; x < 8; ++x) se[x] = 0.f;

        for (int v = u; v < wend; ++v) {
            if (v > u) {
                CP_WAIT1();        // B(v) landed; B(v+1) may be in flight
                __syncthreads();   // visibility; tile v-1 fully consumed
            }
            if (v + 2 < wend)
                load_tile(offB[(v + 2) % 3],
                          g_eH + (size_t)(bi + (v + 2 - offbi)) * 128 * 128, tid);
            CP_COMMIT();           // uniform group counting

            const uint32_t bBuf = offB[v % 3];
            float acc[4][4][4];
            #pragma unroll
            for (int mi = 0; mi < 4; ++mi)
                #pragma unroll
                for (int ni = 0; ni < 4; ++ni)
                    #pragma unroll
                    for (int q = 0; q < 4; ++q) acc[mi][ni][q] = 0.f;

            #pragma unroll
            for (int ks = 0; ks < 8; ++ks) {
                uint32_t b[4][2];
                ldsm4(&b[0][0], bBuf + bRow4 + (((2 * ks + bSel) ^ bXor) << 4));
                ldsm4(&b[2][0], bBuf + bRow4 + 4096 + (((2 * ks + bSel) ^ bXor) << 4));
                #pragma unroll
                for (int mi = 0; mi < 4; ++mi)
                    #pragma unroll
                    for (int ni = 0; ni < 4; ++ni)
                        mma16816(acc[mi][ni], aF[mi][ks], b[ni]);
            }

            const int bj = bi + (v - offbi);
            if (bj != bi) {
                float ce[4][2];
                #pragma unroll
                for (int ni = 0; ni < 4; ++ni) { ce[ni][0] = 0.f; ce[ni][1] = 0.f; }
                #pragma unroll
                for (int ni = 0; ni < 4; ++ni) {
                    #pragma unroll
                    for (int mi = 0; mi < 4; ++mi) {
                        const float* d = acc[mi][ni];
                        float e0 = ex2f(d[0] * TEN_LOG2E);
                        float e1 = ex2f(d[1] * TEN_LOG2E);
                        float e2 = ex2f(d[2] * TEN_LOG2E);
                        float e3 = ex2f(d[3] * TEN_LOG2E);
                        se[mi * 2]     += e0 + e1;
                        se[mi * 2 + 1] += e2 + e3;
                        ce[ni][0] += e0 + e2;
                        ce[ni][1] += e1 + e3;
                    }
                }
                #pragma unroll
                for (int ni = 0; ni < 4; ++ni)
                    #pragma unroll
                    for (int h = 0; h < 2; ++h) {
                        float a0 = ce[ni][h];
                        #pragma unroll
                        for (int off = 4; off <= 16; off <<= 1)
                            a0 += __shfl_xor_sync(0xffffffffu, a0, off);
                        ce[ni][h] = a0;
                    }
                if (lane < 4) {
                    const int cbase = bj * 128 + wn * 32 + 2 * lane;
                    #pragma unroll
                    for (int ni = 0; ni < 4; ++ni) {
                        atomicAdd(&g_sumexp[cbase + ni * 8],     ce[ni][0]);
                        atomicAdd(&g_sumexp[cbase + ni * 8 + 1], ce[ni][1]);
                    }
                }
            } else {
                const int j0 = bj * 128;
                #pragma unroll
                for (int ni = 0; ni < 4; ++ni) {
                    const int gj0 = j0 + wn * 32 + ni * 8 + 2 * (lane & 3);
                    const int gj1 = gj0 + 1;
                    #pragma unroll
                    for (int mi = 0; mi < 4; ++mi) {
                        const int gi0 = i0 + wm * 64 + mi * 16 + (lane >> 2);
                        const int gi1 = gi0 + 8;
                        const float* d = acc[mi][ni];
                        if (gi0 != gj0) se[mi * 2]     += ex2f(d[0] * TEN_LOG2E);
                        if (gi0 != gj1) se[mi * 2]     += ex2f(d[1] * TEN_LOG2E);
                        if (gi1 != gj0) se[mi * 2 + 1] += ex2f(d[2] * TEN_LOG2E);
                        if (gi1 != gj1) se[mi * 2 + 1] += ex2f(d[3] * TEN_LOG2E);
                    }
                }
            }
        }

        #pragma unroll
        for (int x = 0; x < 8; ++x) {
            float s = se[x];
            s += __shfl_xor_sync(0xffffffffu, s, 1);
            s += __shfl_xor_sync(0xffffffffu, s, 2);
            if ((lane & 3) == 0) {
                const int gi = i0 + wm * 64 + (x >> 1) * 16 + (x & 1) * 8 + (lane >> 2);
                atomicAdd(&g_sumexp[gi], s);
            }
        }
        u = wend;
    }
}

// ---------------------------------------------------------------------------
// Kernel 3 (single block): loss = [ sum_i ((cnt-1)*log(se_i) + 10*dii_i)
//   - 10*sum_c |S_c|^2 ] / N ; then RE-ZERO g_S/g_cnt to restore the
// entry invariant for the next kernel_launch call.
// ---------------------------------------------------------------------------
__global__ void finalize_kernel(float* __restrict__ out) {
    __shared__ float red[32];
    const int tid = threadIdx.x;
    const int lane = tid & 31, w = tid >> 5;

    float part = 0.f;
    for (int r = tid; r < NROW; r += 1024) {
        const int lab = g_lab[r];
        part += (float)(g_cnt[lab] - 1) * __logf(g_sumexp[r]) + 10.0f * g_dii[r];
    }
    for (int k = tid; k < NCLS * 128; k += 1024) {
        float s = g_S[k];
        part -= 10.0f * s * s;
    }
    #pragma unroll
    for (int off = 16; off; off >>= 1) part += __shfl_xor_sync(0xffffffffu, part, off);
    if (lane == 0) red[w] = part;
    __syncthreads();            // all g_S/g_cnt reads complete beyond this point
    if (tid < 32) {
        float s = red[tid];
        #pragma unroll
        for (int off = 16; off; off >>= 1) s += __shfl_xor_sync(0xffffffffu, s, off);
        if (tid == 0) out[0] = s / (float)NROW;
    }
    // restore the zero invariant for the next call
    for (int k = tid; k < NCLS * 128; k += 1024) g_S[k] = 0.f;
    if (tid < NCLS) g_cnt[tid] = 0;
}

extern "C" void kernel_launch(void* const* d_in, const int* in_sizes, int n_in,
                              void* d_out, int out_size) {
    const float* emb = (const float*)d_in[0];
    const int* lab   = (const int*)d_in[1];    // dtype sniffed on device
    float* out       = (float*)d_out;

    int nsm = 148;
    cudaDeviceGetAttribute(&nsm, cudaDevAttrMultiProcessorCount, 0);

    const int smem_bytes = 1024 + 4 * 32768;   // 132096
    cudaFuncSetAttribute(sim_kernel, cudaFuncAttributeMaxDynamicSharedMemorySize,
                         smem_bytes);

    prep_kernel<<<NROW / 8, 256>>>(emb, lab);
    sim_kernel<<<nsm, 256, smem_bytes>>>();
    finalize_kernel<<<1, 1024>>>(out);
}

// round 16
// speedup vs baseline: 1.0744x; 1.0744x over previous
#include <cuda_runtime.h>
#include <cuda_fp16.h>
#include <cstdint>

#define NROW 8192
#define TOTUNITS 2080                 // 64*65/2 upper-triangle tiles
#define NCLS 100
#define TEN_LOG2E 14.4269504088896f   // 10 * log2(e)

// -------------------- device globals (no allocations allowed) ---------------
__device__ __align__(256) __half g_eH[NROW * 128];  // normalized, fp16
__device__ __align__(256) int g_lab[NROW];
__device__ float g_sumexp[NROW];
__device__ float g_dii[NROW];          // fp32 self-dot of the fp16 row
__device__ __align__(256) float g_S[NCLS * 128];    // per-class sums
__device__ int g_cnt[NCLS];

// -------------------- PTX helpers (base ISA only) ---------------------------
__device__ __forceinline__ uint32_t smem_u32(const void* p) {
    uint32_t a;
    asm("{ .reg .u64 t; cvta.to.shared.u64 t, %1; cvt.u32.u64 %0, t; }" : "=r"(a) : "l"(p));
    return a;
}
__device__ __forceinline__ float ex2f(float x) {
    float y; asm("ex2.approx.f32 %0, %1;" : "=f"(y) : "f"(x)); return y;
}
__device__ __forceinline__ void cp16(uint32_t dst, const void* src) {
    asm volatile("cp.async.cg.shared.global [%0], [%1], 16;" :: "r"(dst), "l"(src));
}
#define CP_COMMIT() asm volatile("cp.async.commit_group;" ::: "memory")
#define CP_WAIT1()  asm volatile("cp.async.wait_group 1;" ::: "memory")

__device__ __forceinline__ void ldsm4(uint32_t* r, uint32_t addr) {
    asm volatile("ldmatrix.sync.aligned.m8n8.x4.shared.b16 {%0,%1,%2,%3}, [%4];"
        : "=r"(r[0]), "=r"(r[1]), "=r"(r[2]), "=r"(r[3]) : "r"(addr));
}
__device__ __forceinline__ void mma16816(float* d, const uint32_t* a, const uint32_t* b) {
    asm volatile(
        "mma.sync.aligned.m16n8k16.row.col.f32.f16.f16.f32 "
        "{%0,%1,%2,%3}, {%4,%5,%6,%7}, {%8,%9}, {%0,%1,%2,%3};"
        : "+f"(d[0]), "+f"(d[1]), "+f"(d[2]), "+f"(d[3])
        : "r"(a[0]), "r"(a[1]), "r"(a[2]), "r"(a[3]), "r"(b[0]), "r"(b[1]));
}

// Tile: 128 rows x 256B (128 fp16); 16B chunk c stored at c ^ (r & 7).
// Cooperative load by all 256 threads (8 cp.async each).
__device__ __forceinline__ void load_tile(uint32_t dst, const __half* g, int tid) {
    const char* gb = (const char*)g;
    #pragma unroll
    for (int it = 0; it < 8; ++it) {
        int q = tid + it * 256;
        int r = q >> 4, c = q & 15;
        cp16(dst + r * 256 + ((c ^ (r & 7)) * 16), gb + r * 256 + c * 16);
    }
}

__device__ __forceinline__ int tri_off(int bi) { return bi * (129 - bi) / 2; }

// ---------------------------------------------------------------------------
// Kernel 0: sniff labels (int32 vs int64) + convert; zero g_S/g_cnt/out
// ---------------------------------------------------------------------------
__global__ void init_kernel(const int* __restrict__ raw, float* __restrict__ out) {
    __shared__ int s_or;
    const int tid = threadIdx.x, b = blockIdx.x;
    if (tid == 0) { s_or = 0; if (b == 0) out[0] = 0.0f; }
    __syncthreads();
    int local = 0;
    for (int i = tid; i < 2048; i += 256) local |= raw[2 * i + 1];
    if (local) atomicOr(&s_or, 1);
    for (int i = b * 256 + tid; i < NCLS * 128; i += 16 * 256) g_S[i] = 0.0f;
    if (b == 0 && tid < NCLS) g_cnt[tid] = 0;
    __syncthreads();
    const bool is32 = (s_or != 0);
    const int base = b * (NROW / 16);
    for (int i = base + tid; i < base + NROW / 16; i += 256)
        g_lab[i] = is32 ? raw[i] : raw[2 * i];
}

// ---------------------------------------------------------------------------
// Kernel 1: L2-normalize, fp16 convert, self-dot, class-sum atomics; zero se.
// FOUR rows per warp, interleaved chains for ILP (prep was latency-bound).
// ---------------------------------------------------------------------------
__global__ void prep_kernel(const float* __restrict__ emb) {
    const int gtid = blockIdx.x * blockDim.x + threadIdx.x;
    const int warp = gtid >> 5;          // 0..2047
    const int lane = gtid & 31;
    const int row0 = warp * 4;

    // 4 independent load chains in flight
    float4 v[4];
    #pragma unroll
    for (int rr = 0; rr < 4; ++rr)
        v[rr] = reinterpret_cast<const float4*>(emb + (size_t)(row0 + rr) * 128)[lane];

    float ss[4];
    #pragma unroll
    for (int rr = 0; rr < 4; ++rr)
        ss[rr] = v[rr].x * v[rr].x + v[rr].y * v[rr].y
               + v[rr].z * v[rr].z + v[rr].w * v[rr].w;
    #pragma unroll
    for (int off = 16; off; off >>= 1)
        #pragma unroll
        for (int rr = 0; rr < 4; ++rr)
            ss[rr] += __shfl_xor_sync(0xffffffffu, ss[rr], off);

    float2 f0[4], f1[4];
    #pragma unroll
    for (int rr = 0; rr < 4; ++rr) {
        float inv = 1.0f / fmaxf(sqrtf(ss[rr]), 1e-12f);
        __half2 h0 = __floats2half2_rn(v[rr].x * inv, v[rr].y * inv);
        __half2 h1 = __floats2half2_rn(v[rr].z * inv, v[rr].w * inv);
        uint2 pk;
        pk.x = *reinterpret_cast<uint32_t*>(&h0);
        pk.y = *reinterpret_cast<uint32_t*>(&h1);
        reinterpret_cast<uint2*>(g_eH + (size_t)(row0 + rr) * 128)[lane] = pk;
        f0[rr] = __half22float2(h0);
        f1[rr] = __half22float2(h1);
    }

    float d2[4];
    #pragma unroll
    for (int rr = 0; rr < 4; ++rr)
        d2[rr] = f0[rr].x * f0[rr].x + f0[rr].y * f0[rr].y
               + f1[rr].x * f1[rr].x + f1[rr].y * f1[rr].y;
    #pragma unroll
    for (int off = 16; off; off >>= 1)
        #pragma unroll
        for (int rr = 0; rr < 4; ++rr)
            d2[rr] += __shfl_xor_sync(0xffffffffu, d2[rr], off);

    #pragma unroll
    for (int rr = 0; rr < 4; ++rr) {
        const int lab = g_lab[row0 + rr];
        float* sc = g_S + lab * 128 + 4 * lane;
        atomicAdd(sc + 0, f0[rr].x);
        atomicAdd(sc + 1, f0[rr].y);
        atomicAdd(sc + 2, f1[rr].x);
        atomicAdd(sc + 3, f1[rr].y);
        if (lane == 0) {
            g_dii[row0 + rr] = d2[rr];
            g_sumexp[row0 + rr] = 0.f;
            atomicAdd(&g_cnt[lab], 1);
        }
    }
}

// ---------------------------------------------------------------------------
// Kernel 2: persistent fp16 HMMA, upper triangle, 8 warps (64x32 warp tile).
// A fragments register-cached per segment; B via ldsm4.  [round-14, verbatim]
// ---------------------------------------------------------------------------
__global__ __launch_bounds__(256, 1) void sim_kernel() {
    extern __shared__ char smem[];
    const uint32_t sbase = smem_u32(smem);
    const uint32_t abase = (sbase + 1023) & ~1023u;
    const uint32_t offA = abase;
    const uint32_t offB[3] = {abase + 32768, abase + 65536, abase + 98304};

    const int tid = threadIdx.x, lane = tid & 31, wid = tid >> 5;
    const int wm = wid & 1, wn = wid >> 1;

    const int asw = lane & 7;
    const uint32_t aRow = offA + (wm * 64 + (lane & 15)) * 256;
    const int aHalf = lane >> 4;
    const uint32_t bRow4 = (wn * 32 + ((lane >> 4) << 3) + (lane & 7)) * 256;
    const int bSel = (lane >> 3) & 1;
    const int bXor = lane & 7;

    const int G = gridDim.x, cta = blockIdx.x;
    int u = (int)(((long long)cta * TOTUNITS) / G);
    const int w1 = (int)(((long long)(cta + 1) * TOTUNITS) / G);

    while (u < w1) {
        int bi = (int)((129.0 - sqrt(129.0 * 129.0 - 8.0 * (double)u)) * 0.5);
        while (tri_off(bi) > u) --bi;
        while (tri_off(bi + 1) <= u) ++bi;
        const int offbi = tri_off(bi);
        const int wend = min(w1, tri_off(bi + 1));
        const int i0 = bi * 128;

        __syncthreads();   // prev segment's buffer reads complete
        load_tile(offA, g_eH + (size_t)i0 * 128, tid);
        load_tile(offB[u % 3], g_eH + (size_t)(bi + (u - offbi)) * 128 * 128, tid);
        CP_COMMIT();       // group: A + B(u)
        if (u + 1 < wend)
            load_tile(offB[(u + 1) % 3],
                      g_eH + (size_t)(bi + (u + 1 - offbi)) * 128 * 128, tid);
        CP_COMMIT();       // group: B(u+1)
        CP_WAIT1();        // A + B(u) landed
        __syncthreads();

        // cache ALL A fragments for this segment (128 regs)
        uint32_t aF[4][8][4];
        #pragma unroll
        for (int mi = 0; mi < 4; ++mi)
            #pragma unroll
            for (int ks = 0; ks < 8; ++ks)
                ldsm4(aF[mi][ks], aRow + mi * 4096 + (((2 * ks + aHalf) ^ asw) << 4));

        float se[8];
        #pragma unroll
        for (int x = 0; x < 8; ++x) se[x] = 0.f;

        for (int v = u; v < wend; ++v) {
            if (v > u) {
                CP_WAIT1();        // B(v) landed; B(v+1) may be in flight
                __syncthreads();   // visibility; tile v-1 fully consumed
            }
            if (v + 2 < wend)
                load_tile(offB[(v + 2) % 3],
                          g_eH + (size_t)(bi + (v + 2 - offbi)) * 128 * 128, tid);
            CP_COMMIT();           // uniform group counting

            const uint32_t bBuf = offB[v % 3];
            float acc[4][4][4];
            #pragma unroll
            for (int mi = 0; mi < 4; ++mi)
                #pragma unroll
                for (int ni = 0; ni < 4; ++ni)
                    #pragma unroll
                    for (int q = 0; q < 4; ++q) acc[mi][ni][q] = 0.f;

            #pragma unroll
            for (int ks = 0; ks < 8; ++ks) {
                uint32_t b[4][2];
                ldsm4(&b[0][0], bBuf + bRow4 + (((2 * ks + bSel) ^ bXor) << 4));
                ldsm4(&b[2][0], bBuf + bRow4 + 4096 + (((2 * ks + bSel) ^ bXor) << 4));
                #pragma unroll
                for (int mi = 0; mi < 4; ++mi)
                    #pragma unroll
                    for (int ni = 0; ni < 4; ++ni)
                        mma16816(acc[mi][ni], aF[mi][ks], b[ni]);
            }

            const int bj = bi + (v - offbi);
            if (bj != bi) {
                float ce[4][2];
                #pragma unroll
                for (int ni = 0; ni < 4; ++ni) { ce[ni][0] = 0.f; ce[ni][1] = 0.f; }
                #pragma unroll
                for (int ni = 0; ni < 4; ++ni) {
                    #pragma unroll
                    for (int mi = 0; mi < 4; ++mi) {
                        const float* d = acc[mi][ni];
                        float e0 = ex2f(d[0] * TEN_LOG2E);
                        float e1 = ex2f(d[1] * TEN_LOG2E);
                        float e2 = ex2f(d[2] * TEN_LOG2E);
                        float e3 = ex2f(d[3] * TEN_LOG2E);
                        se[mi * 2]     += e0 + e1;
                        se[mi * 2 + 1] += e2 + e3;
                        ce[ni][0] += e0 + e2;
                        ce[ni][1] += e1 + e3;
                    }
                }
                #pragma unroll
                for (int ni = 0; ni < 4; ++ni)
                    #pragma unroll
                    for (int h = 0; h < 2; ++h) {
                        float a0 = ce[ni][h];
                        #pragma unroll
                        for (int off = 4; off <= 16; off <<= 1)
                            a0 += __shfl_xor_sync(0xffffffffu, a0, off);
                        ce[ni][h] = a0;
                    }
                if (lane < 4) {
                    const int cbase = bj * 128 + wn * 32 + 2 * lane;
                    #pragma unroll
                    for (int ni = 0; ni < 4; ++ni) {
                        atomicAdd(&g_sumexp[cbase + ni * 8],     ce[ni][0]);
                        atomicAdd(&g_sumexp[cbase + ni * 8 + 1], ce[ni][1]);
                    }
                }
            } else {
                const int j0 = bj * 128;
                #pragma unroll
                for (int ni = 0; ni < 4; ++ni) {
                    const int gj0 = j0 + wn * 32 + ni * 8 + 2 * (lane & 3);
                    const int gj1 = gj0 + 1;
                    #pragma unroll
                    for (int mi = 0; mi < 4; ++mi) {
                        const int gi0 = i0 + wm * 64 + mi * 16 + (lane >> 2);
                        const int gi1 = gi0 + 8;
                        const float* d = acc[mi][ni];
                        if (gi0 != gj0) se[mi * 2]     += ex2f(d[0] * TEN_LOG2E);
                        if (gi0 != gj1) se[mi * 2]     += ex2f(d[1] * TEN_LOG2E);
                        if (gi1 != gj0) se[mi * 2 + 1] += ex2f(d[2] * TEN_LOG2E);
                        if (gi1 != gj1) se[mi * 2 + 1] += ex2f(d[3] * TEN_LOG2E);
                    }
                }
            }
        }

        #pragma unroll
        for (int x = 0; x < 8; ++x) {
            float s = se[x];
            s += __shfl_xor_sync(0xffffffffu, s, 1);
            s += __shfl_xor_sync(0xffffffffu, s, 2);
            if ((lane & 3) == 0) {
                const int gi = i0 + wm * 64 + (x >> 1) * 16 + (x & 1) * 8 + (lane >> 2);
                atomicAdd(&g_sumexp[gi], s);
            }
        }
        u = wend;
    }
}

// ---------------------------------------------------------------------------
// Kernel 3: loss = [ sum_i (np_i*log(se_i) + 10*dii_i) - 10*sum_c |S_c|^2 ] / N
// ---------------------------------------------------------------------------
__global__ void finalize_kernel(float* __restrict__ out) {
    __shared__ float red[8];
    const int t = blockIdx.x * 256 + threadIdx.x;
    const int lane = threadIdx.x & 31, w = threadIdx.x >> 5;
    const int lab = g_lab[t];
    float part = (float)(g_cnt[lab] - 1) * logf(g_sumexp[t]) + 10.0f * g_dii[t];
    for (int k = t; k < NCLS * 128; k += 8192) {
        float s = g_S[k];
        part -= 10.0f * s * s;
    }
    #pragma unroll
    for (int off = 16; off; off >>= 1) part += __shfl_xor_sync(0xffffffffu, part, off);
    if (lane == 0) red[w] = part;
    __syncthreads();
    if (threadIdx.x < 8) {
        float s = red[threadIdx.x];
        #pragma unroll
        for (int off = 4; off; off >>= 1) s += __shfl_xor_sync(0xffu, s, off);
        if (threadIdx.x == 0) atomicAdd(out, s / (float)NROW);
    }
}

extern "C" void kernel_launch(void* const* d_in, const int* in_sizes, int n_in,
                              void* d_out, int out_size) {
    const float* emb = (const float*)d_in[0];
    const int* lab   = (const int*)d_in[1];    // dtype sniffed on device
    float* out       = (float*)d_out;

    int nsm = 148;
    cudaDeviceGetAttribute(&nsm, cudaDevAttrMultiProcessorCount, 0);

    const int smem_bytes = 1024 + 4 * 32768;   // 132096
    cudaFuncSetAttribute(sim_kernel, cudaFuncAttributeMaxDynamicSharedMemorySize,
                         smem_bytes);

    init_kernel<<<16, 256>>>(lab, out);
    prep_kernel<<<NROW / 32, 256>>>(emb);
    sim_kernel<<<nsm, 256, smem_bytes>>>();
    finalize_kernel<<<32, 256>>>(out);
}